// round 12
// baseline (speedup 1.0000x reference)
#include <cuda_runtime.h>

// ---------------------------------------------------------------------------
// SAMMCodebook.encode on GB300 (sm_103a) — FFMA2 + double-buffered pipeline.
// RESUBMISSION of R11 unchanged (container infra failed twice; experiment
// never ran). Baseline to beat: R10 FFMA2 at 1715.8 us, fma=58.7%, occ=12.5%.
//
//   h: [N=65536, D=1024] f32, codebook: [K=512, D=1024] f32 -> float out [N]
//   argmin_k ||h_n - c_k||^2 == argmax_k ( <h_n,c_k> - 0.5*||c_k||^2 )
//
//   1) software pipeline: LDG(n+1) -> sync -> compute(n) -> STS(n+1),
//      double-buffered smem (BD=8), one barrier per chunk.
//   2) ||c||^2 hoisted to a separate kernel (-11% fma work in hot loop).
//   3) __launch_bounds__(256,2): 2 CTAs/SM -> 4 warps/SMSP latency hiding.
// ---------------------------------------------------------------------------

#define FMA2(acc, a, b) \
    asm("fma.rn.f32x2 %0, %1, %2, %0;" : "+l"(acc) : "l"(a), "l"(b))

__device__ float g_csq[512];   // ||c_k||^2

// ---- pass 1: codebook squared norms ---------------------------------------
__global__ void csq_kernel(const float* __restrict__ cb) {
    int k = blockIdx.x;               // 512 blocks
    int t = threadIdx.x;              // 256 threads, D=1024 -> 256 float4
    const float4* row = reinterpret_cast<const float4*>(cb + (size_t)k * 1024);
    float4 v = row[t];
    float s = v.x * v.x + v.y * v.y + v.z * v.z + v.w * v.w;
    #pragma unroll
    for (int o = 16; o; o >>= 1) s += __shfl_xor_sync(0xffffffffu, s, o);
    __shared__ float ws[8];
    if ((t & 31) == 0) ws[t >> 5] = s;
    __syncthreads();
    if (t == 0) {
        float tot = 0.f;
        #pragma unroll
        for (int w = 0; w < 8; w++) tot += ws[w];
        g_csq[k] = tot;
    }
}

// ---- pass 2: fused GEMM + argmin ------------------------------------------
constexpr int BM  = 64;             // rows per CTA
constexpr int BD  = 8;              // D-chunk (double-buffered)
constexpr int KCB = 512;            // codewords, all in one CTA
constexpr int CSS = KCB + 4;        // 516 floats: float4 rows stay 16B-aligned
constexpr int HSS = 2 * BM + 8;     // 136 floats: duplicated {v,v} rows

__global__ __launch_bounds__(256, 2)
void encode_kernel(const float* __restrict__ h, const float* __restrict__ cb,
                   float* __restrict__ out, int N, int D) {
    __shared__ float c_s[2][BD * CSS];   // [buf][d][k]       (transposed)
    __shared__ float h_s[2][BD * HSS];   // [buf][d][2r,2r+1] = {v,v}

    const int tid  = threadIdx.x;
    const int tx   = tid & 31;         // lane: col pairs {g*128 + 4*tx + 2m}
    const int ty   = tid >> 5;         // warp: rows ty*8 .. ty*8+7
    const int base = blockIdx.x * BM;

    unsigned long long acc[8][8];      // [row][colpair] — 2 fp32 lanes each
    #pragma unroll
    for (int i = 0; i < 8; i++)
        #pragma unroll
        for (int p = 0; p < 8; p++) acc[i][p] = 0ull;

    // global->smem staging mapping (256 threads, chunk = 8 d)
    const int hr  = tid >> 2;          // h row 0..63
    const int hd2 = tid & 3;           // which float2 of the 8-chunk
    const int cr  = tid >> 1;          // cb row base 0..127 (+128*i)
    const int cd4 = tid & 1;           // which float4 of the 8-chunk

    float2 hv;
    float4 cv[4];

    // prologue: load + store chunk 0
    hv = *reinterpret_cast<const float2*>(h + (size_t)(base + hr) * D + 2 * hd2);
    #pragma unroll
    for (int i = 0; i < 4; i++)
        cv[i] = *reinterpret_cast<const float4*>(cb + (size_t)(cr + 128 * i) * D + 4 * cd4);
    #pragma unroll
    for (int j = 0; j < 2; j++) {
        float v = j ? hv.y : hv.x;
        *reinterpret_cast<float2*>(&h_s[0][(2 * hd2 + j) * HSS + 2 * hr]) = make_float2(v, v);
    }
    #pragma unroll
    for (int i = 0; i < 4; i++)
        #pragma unroll
        for (int j = 0; j < 4; j++)
            c_s[0][(4 * cd4 + j) * CSS + cr + 128 * i] = (&cv[i].x)[j];

    const int NCH = D / BD;            // 128 chunks
    for (int ch = 0; ch < NCH; ch++) {
        const int buf = ch & 1;

        // issue next chunk's LDG before the barrier — hidden behind compute
        if (ch + 1 < NCH) {
            const int d0 = (ch + 1) * BD;
            hv = *reinterpret_cast<const float2*>(
                h + (size_t)(base + hr) * D + d0 + 2 * hd2);
            #pragma unroll
            for (int i = 0; i < 4; i++)
                cv[i] = *reinterpret_cast<const float4*>(
                    cb + (size_t)(cr + 128 * i) * D + d0 + 4 * cd4);
        }

        __syncthreads();               // chunk ch staged; chunk ch-1 consumed

        #pragma unroll
        for (int d = 0; d < BD; ++d) {
            unsigned long long a2[8];
            const float* hd = &h_s[buf][d * HSS + 16 * ty];
            #pragma unroll
            for (int i = 0; i < 8; i++)                      // broadcast LDS.64
                a2[i] = *reinterpret_cast<const unsigned long long*>(hd + 2 * i);

            unsigned long long b2[8];
            const float* cd = &c_s[buf][d * CSS + 4 * tx];
            #pragma unroll
            for (int g = 0; g < 4; g++) {                    // LDS.128 -> 2 packs
                float4 bq = *reinterpret_cast<const float4*>(cd + g * 128);
                b2[2 * g]     = *reinterpret_cast<unsigned long long*>(&bq.x);
                b2[2 * g + 1] = *reinterpret_cast<unsigned long long*>(&bq.z);
            }

            #pragma unroll
            for (int i = 0; i < 8; i++)
                #pragma unroll
                for (int p = 0; p < 8; p++)
                    FMA2(acc[i][p], a2[i], b2[p]);
        }

        // stage chunk ch+1 into the other buffer (consumed next iteration)
        if (ch + 1 < NCH) {
            const int nb = (ch + 1) & 1;
            #pragma unroll
            for (int j = 0; j < 2; j++) {
                float v = j ? hv.y : hv.x;
                *reinterpret_cast<float2*>(&h_s[nb][(2 * hd2 + j) * HSS + 2 * hr]) =
                    make_float2(v, v);
            }
            #pragma unroll
            for (int i = 0; i < 4; i++)
                #pragma unroll
                for (int j = 0; j < 4; j++)
                    c_s[nb][(4 * cd4 + j) * CSS + cr + 128 * i] = (&cv[i].x)[j];
        }
    }

    // ---- epilogue: score = dot - 0.5*||c||^2, per-row argmax over 512 ----
    float half_csq[16];
    #pragma unroll
    for (int p = 0; p < 8; p++) {
        int col = (p >> 1) * 128 + 4 * tx + (p & 1) * 2;
        float2 cc = *reinterpret_cast<const float2*>(&g_csq[col]);
        half_csq[2 * p]     = 0.5f * cc.x;
        half_csq[2 * p + 1] = 0.5f * cc.y;
    }

    #pragma unroll
    for (int i = 0; i < 8; i++) {
        float bestv = -3.402823466e+38f;
        int   besti = 0x7fffffff;
        #pragma unroll
        for (int p = 0; p < 8; p++) {
            int col = (p >> 1) * 128 + 4 * tx + (p & 1) * 2;
            float lo = __uint_as_float((unsigned)(acc[i][p] & 0xffffffffull));
            float hi = __uint_as_float((unsigned)(acc[i][p] >> 32));
            float v0 = lo - half_csq[2 * p];
            float v1 = hi - half_csq[2 * p + 1];
            if (v0 > bestv || (v0 == bestv && col < besti))       { bestv = v0; besti = col; }
            if (v1 > bestv || (v1 == bestv && (col + 1) < besti)) { bestv = v1; besti = col + 1; }
        }
        #pragma unroll
        for (int o = 16; o; o >>= 1) {   // butterfly: max value, min index on tie
            float ov = __shfl_xor_sync(0xffffffffu, bestv, o);
            int   oi = __shfl_xor_sync(0xffffffffu, besti, o);
            if (ov > bestv || (ov == bestv && oi < besti)) { bestv = ov; besti = oi; }
        }
        if (tx == 0) out[base + ty * 8 + i] = (float)besti;   // FLOAT output
    }
}

// ---------------------------------------------------------------------------
extern "C" void kernel_launch(void* const* d_in, const int* in_sizes, int n_in,
                              void* d_out, int out_size) {
    const int D = 1024;

    // Runtime input-order disambiguation: h (67.1M elems) vs codebook (0.52M).
    const float* h;
    const float* cb;
    int N;
    if (in_sizes[0] >= in_sizes[1]) {
        h  = (const float*)d_in[0];  N = in_sizes[0] / D;
        cb = (const float*)d_in[1];
    } else {
        h  = (const float*)d_in[1];  N = in_sizes[1] / D;
        cb = (const float*)d_in[0];
    }
    float* out = (float*)d_out;

    csq_kernel<<<512, 256>>>(cb);
    encode_kernel<<<N / BM, 256>>>(h, cb, out, N, D);
}

// round 13
// speedup vs baseline: 5.6125x; 5.6125x over previous
#include <cuda_runtime.h>

// ---------------------------------------------------------------------------
// SAMMCodebook.encode on GB300 (sm_103a) — FFMA2 + double-buffered pipeline,
// occupancy 1 (R12 post-mortem: __launch_bounds__(256,2) capped regs at 128,
// but acc alone = 64 x u64 = 128 regs -> full accumulator spill, 5.3x
// regression with fma=13%, L1=84%. Occupancy is NOT a lever for this tile.)
//
//   h: [N=65536, D=1024] f32, codebook: [K=512, D=1024] f32 -> float out [N]
//   argmin_k ||h_n - c_k||^2 == argmax_k ( <h_n,c_k> - 0.5*||c_k||^2 )
//
// Kept from R11: software pipeline LDG(n+1) -> sync -> compute(n) -> STS(n+1)
// with double-buffered smem (BD=8, one barrier per chunk), and ||c||^2
// hoisted out of the hot loop (-11% fma work).
// ---------------------------------------------------------------------------

#define FMA2(acc, a, b) \
    asm("fma.rn.f32x2 %0, %1, %2, %0;" : "+l"(acc) : "l"(a), "l"(b))

__device__ float g_csq[512];   // ||c_k||^2

// ---- pass 1: codebook squared norms ---------------------------------------
__global__ void csq_kernel(const float* __restrict__ cb) {
    int k = blockIdx.x;               // 512 blocks
    int t = threadIdx.x;              // 256 threads, D=1024 -> 256 float4
    const float4* row = reinterpret_cast<const float4*>(cb + (size_t)k * 1024);
    float4 v = row[t];
    float s = v.x * v.x + v.y * v.y + v.z * v.z + v.w * v.w;
    #pragma unroll
    for (int o = 16; o; o >>= 1) s += __shfl_xor_sync(0xffffffffu, s, o);
    __shared__ float ws[8];
    if ((t & 31) == 0) ws[t >> 5] = s;
    __syncthreads();
    if (t == 0) {
        float tot = 0.f;
        #pragma unroll
        for (int w = 0; w < 8; w++) tot += ws[w];
        g_csq[k] = tot;
    }
}

// ---- pass 2: fused GEMM + argmin ------------------------------------------
constexpr int BM  = 64;             // rows per CTA
constexpr int BD  = 8;              // D-chunk (double-buffered)
constexpr int KCB = 512;            // codewords, all in one CTA
constexpr int CSS = KCB + 4;        // 516 floats: float4 rows stay 16B-aligned
constexpr int HSS = 2 * BM + 8;     // 136 floats: duplicated {v,v} rows

__global__ __launch_bounds__(256)
void encode_kernel(const float* __restrict__ h, const float* __restrict__ cb,
                   float* __restrict__ out, int N, int D) {
    __shared__ float c_s[2][BD * CSS];   // [buf][d][k]       (transposed)
    __shared__ float h_s[2][BD * HSS];   // [buf][d][2r,2r+1] = {v,v}

    const int tid  = threadIdx.x;
    const int tx   = tid & 31;         // lane: col pairs {g*128 + 4*tx + 2m}
    const int ty   = tid >> 5;         // warp: rows ty*8 .. ty*8+7
    const int base = blockIdx.x * BM;

    unsigned long long acc[8][8];      // [row][colpair] — 2 fp32 lanes each
    #pragma unroll
    for (int i = 0; i < 8; i++)
        #pragma unroll
        for (int p = 0; p < 8; p++) acc[i][p] = 0ull;

    // global->smem staging mapping (256 threads, chunk = 8 d)
    const int hr  = tid >> 2;          // h row 0..63
    const int hd2 = tid & 3;           // which float2 of the 8-chunk
    const int cr  = tid >> 1;          // cb row base 0..127 (+128*i)
    const int cd4 = tid & 1;           // which float4 of the 8-chunk

    float2 hv;
    float4 cv[4];

    // prologue: load + store chunk 0
    hv = *reinterpret_cast<const float2*>(h + (size_t)(base + hr) * D + 2 * hd2);
    #pragma unroll
    for (int i = 0; i < 4; i++)
        cv[i] = *reinterpret_cast<const float4*>(cb + (size_t)(cr + 128 * i) * D + 4 * cd4);
    #pragma unroll
    for (int j = 0; j < 2; j++) {
        float v = j ? hv.y : hv.x;
        *reinterpret_cast<float2*>(&h_s[0][(2 * hd2 + j) * HSS + 2 * hr]) = make_float2(v, v);
    }
    #pragma unroll
    for (int i = 0; i < 4; i++)
        #pragma unroll
        for (int j = 0; j < 4; j++)
            c_s[0][(4 * cd4 + j) * CSS + cr + 128 * i] = (&cv[i].x)[j];

    const int NCH = D / BD;            // 128 chunks
    for (int ch = 0; ch < NCH; ch++) {
        const int buf = ch & 1;

        // issue next chunk's LDG before the barrier — hidden behind compute
        if (ch + 1 < NCH) {
            const int d0 = (ch + 1) * BD;
            hv = *reinterpret_cast<const float2*>(
                h + (size_t)(base + hr) * D + d0 + 2 * hd2);
            #pragma unroll
            for (int i = 0; i < 4; i++)
                cv[i] = *reinterpret_cast<const float4*>(
                    cb + (size_t)(cr + 128 * i) * D + d0 + 4 * cd4);
        }

        __syncthreads();               // chunk ch staged; chunk ch-1 consumed

        #pragma unroll
        for (int d = 0; d < BD; ++d) {
            unsigned long long a2[8];
            const float* hd = &h_s[buf][d * HSS + 16 * ty];
            #pragma unroll
            for (int i = 0; i < 8; i++)                      // broadcast LDS.64
                a2[i] = *reinterpret_cast<const unsigned long long*>(hd + 2 * i);

            unsigned long long b2[8];
            const float* cd = &c_s[buf][d * CSS + 4 * tx];
            #pragma unroll
            for (int g = 0; g < 4; g++) {                    // LDS.128 -> 2 packs
                float4 bq = *reinterpret_cast<const float4*>(cd + g * 128);
                b2[2 * g]     = *reinterpret_cast<unsigned long long*>(&bq.x);
                b2[2 * g + 1] = *reinterpret_cast<unsigned long long*>(&bq.z);
            }

            #pragma unroll
            for (int i = 0; i < 8; i++)
                #pragma unroll
                for (int p = 0; p < 8; p++)
                    FMA2(acc[i][p], a2[i], b2[p]);
        }

        // stage chunk ch+1 into the other buffer (consumed next iteration)
        if (ch + 1 < NCH) {
            const int nb = (ch + 1) & 1;
            #pragma unroll
            for (int j = 0; j < 2; j++) {
                float v = j ? hv.y : hv.x;
                *reinterpret_cast<float2*>(&h_s[nb][(2 * hd2 + j) * HSS + 2 * hr]) =
                    make_float2(v, v);
            }
            #pragma unroll
            for (int i = 0; i < 4; i++)
                #pragma unroll
                for (int j = 0; j < 4; j++)
                    c_s[nb][(4 * cd4 + j) * CSS + cr + 128 * i] = (&cv[i].x)[j];
        }
    }

    // ---- epilogue: score = dot - 0.5*||c||^2, per-row argmax over 512 ----
    float half_csq[16];
    #pragma unroll
    for (int p = 0; p < 8; p++) {
        int col = (p >> 1) * 128 + 4 * tx + (p & 1) * 2;
        float2 cc = *reinterpret_cast<const float2*>(&g_csq[col]);
        half_csq[2 * p]     = 0.5f * cc.x;
        half_csq[2 * p + 1] = 0.5f * cc.y;
    }

    #pragma unroll
    for (int i = 0; i < 8; i++) {
        float bestv = -3.402823466e+38f;
        int   besti = 0x7fffffff;
        #pragma unroll
        for (int p = 0; p < 8; p++) {
            int col = (p >> 1) * 128 + 4 * tx + (p & 1) * 2;
            float lo = __uint_as_float((unsigned)(acc[i][p] & 0xffffffffull));
            float hi = __uint_as_float((unsigned)(acc[i][p] >> 32));
            float v0 = lo - half_csq[2 * p];
            float v1 = hi - half_csq[2 * p + 1];
            if (v0 > bestv || (v0 == bestv && col < besti))       { bestv = v0; besti = col; }
            if (v1 > bestv || (v1 == bestv && (col + 1) < besti)) { bestv = v1; besti = col + 1; }
        }
        #pragma unroll
        for (int o = 16; o; o >>= 1) {   // butterfly: max value, min index on tie
            float ov = __shfl_xor_sync(0xffffffffu, bestv, o);
            int   oi = __shfl_xor_sync(0xffffffffu, besti, o);
            if (ov > bestv || (ov == bestv && oi < besti)) { bestv = ov; besti = oi; }
        }
        if (tx == 0) out[base + ty * 8 + i] = (float)besti;   // FLOAT output
    }
}

// ---------------------------------------------------------------------------
extern "C" void kernel_launch(void* const* d_in, const int* in_sizes, int n_in,
                              void* d_out, int out_size) {
    const int D = 1024;

    // Runtime input-order disambiguation: h (67.1M elems) vs codebook (0.52M).
    const float* h;
    const float* cb;
    int N;
    if (in_sizes[0] >= in_sizes[1]) {
        h  = (const float*)d_in[0];  N = in_sizes[0] / D;
        cb = (const float*)d_in[1];
    } else {
        h  = (const float*)d_in[1];  N = in_sizes[1] / D;
        cb = (const float*)d_in[0];
    }
    float* out = (float*)d_out;

    csq_kernel<<<512, 256>>>(cb);
    encode_kernel<<<N / BM, 256>>>(h, cb, out, N, D);
}

// round 15
// speedup vs baseline: 6.0597x; 1.0797x over previous
#include <cuda_runtime.h>
#include <cuda_bf16.h>
#include <cstdint>

// ---------------------------------------------------------------------------
// SAMMCodebook.encode on GB300 (sm_103a) — legacy HMMA (mma.sync bf16) path.
// R14 post-mortem: harness compiles via compute_103 (no 'a') -> tcgen05/TMEM
// unavailable. mma.sync.m16n8k16 bf16 is baseline PTX and runs on the tensor
// pipe as HMMA. Same algorithm: 3-term bf16 hi/lo split GEMM (hh+hl+lh),
// fp32 accum, margin-gated exact fp32 refinement.
//   h:[65536,1024]f32, cb:[512,1024]f32 -> float out[65536]
//   argmin_k ||h-c_k||^2 == argmin_k (0.5||c_k||^2 - <h,c_k>)
// ---------------------------------------------------------------------------

__device__ float    g_csq[512];
__device__ unsigned g_cbhi[512 * 512];   // u32-packed bf16 pairs, [k][512]
__device__ unsigned g_cblo[512 * 512];
__device__ float    g_margin[65536];

__device__ __forceinline__ uint32_t pack_bf(__nv_bfloat16 a, __nv_bfloat16 b) {
    return (uint32_t)__bfloat16_as_ushort(a) |
           ((uint32_t)__bfloat16_as_ushort(b) << 16);
}
// u32-column permutation so fragment (a0,a2)/(a1,a3)/(b0,b1) pairs are one LDS.64
__device__ __forceinline__ int PERM(int c) {
    return ((c & 3) << 1) | ((c >> 2) & 1) | (c & 8);
}

// ---- phase 0: csq + bf16 hi/lo split of the codebook -----------------------
__global__ void prep_kernel(const float* __restrict__ cb) {
    int k = blockIdx.x;               // 512 blocks
    int t = threadIdx.x;              // 256 threads; 4 floats each
    float4 v = reinterpret_cast<const float4*>(cb + (size_t)k * 1024)[t];
    float s = v.x * v.x + v.y * v.y + v.z * v.z + v.w * v.w;
    #pragma unroll
    for (int o = 16; o; o >>= 1) s += __shfl_xor_sync(0xffffffffu, s, o);
    __shared__ float ws[8];
    if ((t & 31) == 0) ws[t >> 5] = s;
    __syncthreads();
    if (t == 0) {
        float tot = 0.f;
        #pragma unroll
        for (int w = 0; w < 8; w++) tot += ws[w];
        g_csq[k] = tot;
    }
    __nv_bfloat16 b0 = __float2bfloat16(v.x), b1 = __float2bfloat16(v.y),
                  b2 = __float2bfloat16(v.z), b3 = __float2bfloat16(v.w);
    float l0 = v.x - __bfloat162float(b0), l1 = v.y - __bfloat162float(b1),
          l2 = v.z - __bfloat162float(b2), l3 = v.w - __bfloat162float(b3);
    g_cbhi[k * 512 + 2 * t]     = pack_bf(b0, b1);
    g_cbhi[k * 512 + 2 * t + 1] = pack_bf(b2, b3);
    g_cblo[k * 512 + 2 * t]     = pack_bf(__float2bfloat16(l0), __float2bfloat16(l1));
    g_cblo[k * 512 + 2 * t + 1] = pack_bf(__float2bfloat16(l2), __float2bfloat16(l3));
}

// ---- phase 1: HMMA GEMM + approximate argmin + margin ----------------------
constexpr int RS   = 20;            // u32 row stride (bank-conflict-free)
constexpr int TILE = 128 * RS;      // 2560 u32 per tile
constexpr int BUF  = 4 * TILE;      // Ahi, Alo, Bhi, Blo
constexpr int SMEM_BYTES = (1024 + 2 * BUF) * 4;   // 86016

__device__ __forceinline__ void mma_bf16(float* d, uint32_t a0, uint32_t a1,
                                         uint32_t a2, uint32_t a3,
                                         uint32_t b0, uint32_t b1) {
    asm volatile(
        "mma.sync.aligned.m16n8k16.row.col.f32.bf16.bf16.f32 "
        "{%0,%1,%2,%3}, {%4,%5,%6,%7}, {%8,%9}, {%0,%1,%2,%3};"
        : "+f"(d[0]), "+f"(d[1]), "+f"(d[2]), "+f"(d[3])
        : "r"(a0), "r"(a1), "r"(a2), "r"(a3), "r"(b0), "r"(b1));
}

__global__ __launch_bounds__(256)
void encode_main(const float* __restrict__ h, float* __restrict__ out, int N) {
    extern __shared__ uint32_t smem[];
    float* csq_s = reinterpret_cast<float*>(smem);                         // 512 f
    unsigned long long* best1u = reinterpret_cast<unsigned long long*>(smem + 512);
    unsigned long long* best2u = reinterpret_cast<unsigned long long*>(smem + 768);
    uint32_t* tiles = smem + 1024;

    const int tid  = threadIdx.x;
    const int lane = tid & 31, wid = tid >> 5;
    const int g = lane >> 2, tc = lane & 3;
    const int wm = wid >> 2, wn = wid & 3;       // 2 x 4 warp grid
    const int base = blockIdx.x * 128;
    const float* hA = h + (size_t)base * 1024;

    csq_s[tid]       = g_csq[tid];
    csq_s[tid + 256] = g_csq[tid + 256];

    unsigned long long b1 = ~0ull, b2 = ~0ull;   // running (score||col) keys
    float acc[4][4][4];

    const int sr  = tid >> 3;     // staging row 0..127
    const int sf  = tid & 7;      // staging sub-index 0..7

    for (int nblk = 0; nblk < 4; nblk++) {
        const int nbase = nblk * 128;
        #pragma unroll
        for (int mi = 0; mi < 4; mi++)
            #pragma unroll
            for (int ni = 0; ni < 4; ni++)
                #pragma unroll
                for (int f = 0; f < 4; f++) acc[mi][ni][f] = 0.f;

        float4 av[4];
        unsigned long long bh[4], bl[4];

        // ---- prologue: LDG + STS chunk 0 into buffer 0 ----
        #pragma unroll
        for (int i = 0; i < 4; i++) {
            int row = (tid + 256 * i) >> 3, f4 = (tid + 256 * i) & 7;
            av[i] = *reinterpret_cast<const float4*>(hA + (size_t)row * 1024 + 4 * f4);
            const unsigned* ph = g_cbhi + (((size_t)(nbase + row)) << 9) + 2 * f4;
            const unsigned* pl = g_cblo + (((size_t)(nbase + row)) << 9) + 2 * f4;
            bh[i] = *reinterpret_cast<const unsigned long long*>(ph);
            bl[i] = *reinterpret_cast<const unsigned long long*>(pl);
        }
        {
            uint32_t* Ahi = tiles;           uint32_t* Alo = tiles + TILE;
            uint32_t* Bhi = tiles + 2*TILE;  uint32_t* Blo = tiles + 3*TILE;
            #pragma unroll
            for (int i = 0; i < 4; i++) {
                int row = (tid + 256 * i) >> 3, f4 = (tid + 256 * i) & 7;
                float4 v = av[i];
                __nv_bfloat16 x0=__float2bfloat16(v.x), x1=__float2bfloat16(v.y),
                              x2=__float2bfloat16(v.z), x3=__float2bfloat16(v.w);
                float l0=v.x-__bfloat162float(x0), l1=v.y-__bfloat162float(x1),
                      l2=v.z-__bfloat162float(x2), l3=v.w-__bfloat162float(x3);
                Ahi[row*RS + PERM(2*f4)]   = pack_bf(x0, x1);
                Ahi[row*RS + PERM(2*f4+1)] = pack_bf(x2, x3);
                Alo[row*RS + PERM(2*f4)]   = pack_bf(__float2bfloat16(l0), __float2bfloat16(l1));
                Alo[row*RS + PERM(2*f4+1)] = pack_bf(__float2bfloat16(l2), __float2bfloat16(l3));
                Bhi[row*RS + PERM(2*f4)]   = (uint32_t)bh[i];
                Bhi[row*RS + PERM(2*f4+1)] = (uint32_t)(bh[i] >> 32);
                Blo[row*RS + PERM(2*f4)]   = (uint32_t)bl[i];
                Blo[row*RS + PERM(2*f4+1)] = (uint32_t)(bl[i] >> 32);
            }
        }

        for (int ch = 0; ch < 32; ch++) {
            const uint32_t* tb = tiles + (ch & 1) * BUF;

            if (ch + 1 < 32) {            // prefetch next chunk (LDG only)
                const int d0 = (ch + 1) * 32;
                #pragma unroll
                for (int i = 0; i < 4; i++) {
                    int row = (tid + 256 * i) >> 3, f4 = (tid + 256 * i) & 7;
                    av[i] = *reinterpret_cast<const float4*>(
                        hA + (size_t)row * 1024 + d0 + 4 * f4);
                    const unsigned* ph = g_cbhi + (((size_t)(nbase + row)) << 9)
                                         + (ch + 1) * 16 + 2 * f4;
                    const unsigned* pl = g_cblo + (((size_t)(nbase + row)) << 9)
                                         + (ch + 1) * 16 + 2 * f4;
                    bh[i] = *reinterpret_cast<const unsigned long long*>(ph);
                    bl[i] = *reinterpret_cast<const unsigned long long*>(pl);
                }
            }

            __syncthreads();              // chunk ch staged & prior compute done

            const uint32_t* Ahi = tb;            const uint32_t* Alo = tb + TILE;
            const uint32_t* Bhi = tb + 2*TILE;   const uint32_t* Blo = tb + 3*TILE;
            #pragma unroll
            for (int ks = 0; ks < 2; ks++) {
                const int co = 8 * ks + 2 * tc;
                uint2 Ah[4][2], Al[4][2], Bh[4], Bl[4];
                #pragma unroll
                for (int mi = 0; mi < 4; mi++) {
                    int r0 = (wm * 64 + mi * 16 + g) * RS + co;
                    Ah[mi][0] = *reinterpret_cast<const uint2*>(Ahi + r0);
                    Ah[mi][1] = *reinterpret_cast<const uint2*>(Ahi + r0 + 8 * RS);
                    Al[mi][0] = *reinterpret_cast<const uint2*>(Alo + r0);
                    Al[mi][1] = *reinterpret_cast<const uint2*>(Alo + r0 + 8 * RS);
                }
                #pragma unroll
                for (int ni = 0; ni < 4; ni++) {
                    int r0 = (wn * 32 + ni * 8 + g) * RS + co;
                    Bh[ni] = *reinterpret_cast<const uint2*>(Bhi + r0);
                    Bl[ni] = *reinterpret_cast<const uint2*>(Blo + r0);
                }
                #pragma unroll
                for (int mi = 0; mi < 4; mi++)
                    #pragma unroll
                    for (int ni = 0; ni < 4; ni++) {
                        float* d = acc[mi][ni];
                        mma_bf16(d, Ah[mi][0].x, Ah[mi][1].x, Ah[mi][0].y, Ah[mi][1].y,
                                 Bh[ni].x, Bh[ni].y);
                        mma_bf16(d, Ah[mi][0].x, Ah[mi][1].x, Ah[mi][0].y, Ah[mi][1].y,
                                 Bl[ni].x, Bl[ni].y);
                        mma_bf16(d, Al[mi][0].x, Al[mi][1].x, Al[mi][0].y, Al[mi][1].y,
                                 Bh[ni].x, Bh[ni].y);
                    }
            }

            if (ch + 1 < 32) {            // STS next chunk into other buffer
                uint32_t* t2 = tiles + ((ch + 1) & 1) * BUF;
                uint32_t* Ah2 = t2;            uint32_t* Al2 = t2 + TILE;
                uint32_t* Bh2 = t2 + 2*TILE;   uint32_t* Bl2 = t2 + 3*TILE;
                #pragma unroll
                for (int i = 0; i < 4; i++) {
                    int row = (tid + 256 * i) >> 3, f4 = (tid + 256 * i) & 7;
                    float4 v = av[i];
                    __nv_bfloat16 x0=__float2bfloat16(v.x), x1=__float2bfloat16(v.y),
                                  x2=__float2bfloat16(v.z), x3=__float2bfloat16(v.w);
                    float l0=v.x-__bfloat162float(x0), l1=v.y-__bfloat162float(x1),
                          l2=v.z-__bfloat162float(x2), l3=v.w-__bfloat162float(x3);
                    Ah2[row*RS + PERM(2*f4)]   = pack_bf(x0, x1);
                    Ah2[row*RS + PERM(2*f4+1)] = pack_bf(x2, x3);
                    Al2[row*RS + PERM(2*f4)]   = pack_bf(__float2bfloat16(l0), __float2bfloat16(l1));
                    Al2[row*RS + PERM(2*f4+1)] = pack_bf(__float2bfloat16(l2), __float2bfloat16(l3));
                    Bh2[row*RS + PERM(2*f4)]   = (uint32_t)bh[i];
                    Bh2[row*RS + PERM(2*f4+1)] = (uint32_t)(bh[i] >> 32);
                    Bl2[row*RS + PERM(2*f4)]   = (uint32_t)bl[i];
                    Bl2[row*RS + PERM(2*f4+1)] = (uint32_t)(bl[i] >> 32);
                }
            }
        }

        // ---- n-block epilogue: best1/best2 via keyed smem atomicMin ----
        __syncthreads();
        if (tid < 128) { best1u[tid] = ~0ull; best2u[tid] = ~0ull; }
        __syncthreads();

        #pragma unroll
        for (int mi = 0; mi < 4; mi++)
            #pragma unroll
            for (int half = 0; half < 2; half++) {
                int row = wm * 64 + mi * 16 + g + 8 * half;
                unsigned long long kmin = ~0ull;
                #pragma unroll
                for (int ni = 0; ni < 4; ni++)
                    #pragma unroll
                    for (int f = 0; f < 2; f++) {
                        int col = nbase + wn * 32 + ni * 8 + 2 * tc + f;
                        float s = 0.5f * csq_s[col] - acc[mi][ni][2 * half + f];
                        uint32_t u = __float_as_uint(s);
                        uint32_t k32 = (u & 0x80000000u) ? ~u : (u | 0x80000000u);
                        unsigned long long key =
                            ((unsigned long long)k32 << 32) | (unsigned)col;
                        if (key < kmin) kmin = key;
                    }
                atomicMin(&best1u[row], kmin);
            }
        __syncthreads();
        #pragma unroll
        for (int mi = 0; mi < 4; mi++)
            #pragma unroll
            for (int half = 0; half < 2; half++) {
                int row = wm * 64 + mi * 16 + g + 8 * half;
                unsigned bcol = (unsigned)(best1u[row] & 0xffffffffu);
                unsigned long long kmin = ~0ull;
                #pragma unroll
                for (int ni = 0; ni < 4; ni++)
                    #pragma unroll
                    for (int f = 0; f < 2; f++) {
                        int col = nbase + wn * 32 + ni * 8 + 2 * tc + f;
                        if ((unsigned)col == bcol) continue;
                        float s = 0.5f * csq_s[col] - acc[mi][ni][2 * half + f];
                        uint32_t u = __float_as_uint(s);
                        uint32_t k32 = (u & 0x80000000u) ? ~u : (u | 0x80000000u);
                        unsigned long long key =
                            ((unsigned long long)k32 << 32) | (unsigned)col;
                        if (key < kmin) kmin = key;
                    }
                atomicMin(&best2u[row], kmin);
            }
        __syncthreads();
        if (tid < 128) {     // merge this n-block's top-2 into running top-2
            unsigned long long c1 = best1u[tid], c2 = best2u[tid];
            if (c1 < b1) { b2 = (b1 < c2 ? b1 : c2); b1 = c1; }
            else         { b2 = (b2 < c1 ? b2 : c1); }
        }
        __syncthreads();     // best arrays / tiles free for next n-block
    }

    if (tid < 128) {
        uint32_t h1 = (uint32_t)(b1 >> 32), h2 = (uint32_t)(b2 >> 32);
        float s1 = (h1 & 0x80000000u) ? __uint_as_float(h1 & 0x7fffffffu)
                                      : __uint_as_float(~h1);
        float s2 = (h2 & 0x80000000u) ? __uint_as_float(h2 & 0x7fffffffu)
                                      : __uint_as_float(~h2);
        int row = base + tid;
        out[row]      = (float)(unsigned)(b1 & 0xffffffffu);
        g_margin[row] = s2 - s1;
    }
}

// ---- phase 2: exact fp32 refinement for near-tie rows ----------------------
constexpr float TAU = 0.05f;

__global__ __launch_bounds__(256)
void refine_kernel(const float* __restrict__ h, const float* __restrict__ cb,
                   float* __restrict__ out, int N) {
    __shared__ float hrow[1024];
    __shared__ float rmin[256];
    __shared__ int   ridx[256];
    const int base = blockIdx.x * 128;
    const int t = threadIdx.x;

    for (int r = 0; r < 128; r++) {
        int row = base + r;
        if (g_margin[row] >= TAU) continue;      // uniform branch
        __syncthreads();
        for (int i = t; i < 1024; i += 256)
            hrow[i] = h[(size_t)row * 1024 + i];
        __syncthreads();

        float best = 3.402823466e+38f;
        int   bidx = 0x7fffffff;
        for (int k = t; k < 512; k += 256) {
            const float* c = cb + (size_t)k * 1024;
            float dot = 0.f;
            for (int d = 0; d < 1024; d += 4) {
                float4 cv = *reinterpret_cast<const float4*>(c + d);
                dot = fmaf(hrow[d],     cv.x, dot);
                dot = fmaf(hrow[d + 1], cv.y, dot);
                dot = fmaf(hrow[d + 2], cv.z, dot);
                dot = fmaf(hrow[d + 3], cv.w, dot);
            }
            float s = 0.5f * g_csq[k] - dot;
            if (s < best || (s == best && k < bidx)) { best = s; bidx = k; }
        }
        rmin[t] = best; ridx[t] = bidx;
        __syncthreads();
        for (int off = 128; off; off >>= 1) {
            if (t < off) {
                float ov = rmin[t + off]; int oi = ridx[t + off];
                if (ov < rmin[t] || (ov == rmin[t] && oi < ridx[t])) {
                    rmin[t] = ov; ridx[t] = oi;
                }
            }
            __syncthreads();
        }
        if (t == 0) out[row] = (float)ridx[0];
    }
}

// ---------------------------------------------------------------------------
extern "C" void kernel_launch(void* const* d_in, const int* in_sizes, int n_in,
                              void* d_out, int out_size) {
    const int D = 1024;
    const float* h;
    const float* cb;
    int N;
    if (in_sizes[0] >= in_sizes[1]) {
        h  = (const float*)d_in[0];  N = in_sizes[0] / D;
        cb = (const float*)d_in[1];
    } else {
        h  = (const float*)d_in[1];  N = in_sizes[1] / D;
        cb = (const float*)d_in[0];
    }
    float* out = (float*)d_out;

    cudaFuncSetAttribute(encode_main,
                         cudaFuncAttributeMaxDynamicSharedMemorySize, SMEM_BYTES);

    prep_kernel<<<512, 256>>>(cb);
    encode_main<<<N / 128, 256, SMEM_BYTES>>>(h, out, N);
    refine_kernel<<<N / 128, 256>>>(h, cb, out, N);
}